// round 16
// baseline (speedup 1.0000x reference)
#include <cuda_runtime.h>
#include <cstdint>

#define NJ 64
#define DD 32
#define HH 64

// Shared memory layout (float offsets)
#define S_WC   0                    // Wm1 rearranged [32][128] = 4096
#define S_WM2  (S_WC + 4096)        // [64][32] = 2048
#define S_WU1  (S_WM2 + 2048)       // [64][64] = 4096
#define S_WU2  (S_WU1 + 4096)       // [64][32] = 2048
#define S_B    (S_WU2 + 2048)       // bm1[0:64) bm2[64:96) bu1[96:160) bu2[160:192)
#define S_F    (S_B + 192)          // [64][36] = 2304
#define S_M    (S_F + 2304)         // [64][36] = 2304
#define S_G    (S_M + 2304)         // G[64][132]=8448 ; overlays: H[128][68]=8704 ; U[64][68]
#define S_TOTAL (S_G + 8704)        // 25792 floats = 103168 bytes

union F2 { uint64_t u; float2 f; };

__device__ __forceinline__ uint64_t ld2s(const float* p) {
    return *reinterpret_cast<const uint64_t*>(p);
}
__device__ __forceinline__ void fma2(uint64_t& d, uint64_t a, uint64_t b) {
    asm("fma.rn.f32x2 %0, %1, %2, %0;" : "+l"(d) : "l"(a), "l"(b));
}
__device__ __forceinline__ uint64_t dup2(float a) {
    uint64_t r; asm("mov.b64 %0, {%1, %1};" : "=l"(r) : "f"(a)); return r;
}
__device__ __forceinline__ void relu2(uint64_t& v) {
    F2 x; x.u = v;
    x.f.x = fmaxf(x.f.x, 0.f);
    x.f.y = fmaxf(x.f.y, 0.f);
    v = x.u;
}

extern __shared__ float sm[];

__global__ void __launch_bounds__(256, 2)
agn_kernel(const float* __restrict__ Fg,
           const float* __restrict__ Wm1, const float* __restrict__ bm1,
           const float* __restrict__ Wm2, const float* __restrict__ bm2,
           const float* __restrict__ Wu1, const float* __restrict__ bu1,
           const float* __restrict__ Wu2, const float* __restrict__ bu2,
           const float* __restrict__ rwp,
           float* __restrict__ Og, int B)
{
    const int t = threadIdx.x;

    // ================= one-time: stage weights / biases, zero H pad rows ==========
    // Wc[32][128]: Wc[k][c] = Wm1[k][c] for c<64 ; Wm1[k+32][c-64] for c>=64
    #pragma unroll
    for (int i = 0; i < 16; i++) {
        int gi = t + i * 256;
        int kg = gi >> 6, h = gi & 63;
        sm[S_WC + (kg & 31) * 128 + (kg >> 5) * 64 + h] = Wm1[gi];
    }
    #pragma unroll
    for (int i = 0; i < 2; i++) {
        int g = t + i * 256;
        reinterpret_cast<float4*>(sm + S_WM2)[g] = reinterpret_cast<const float4*>(Wm2)[g];
    }
    #pragma unroll
    for (int i = 0; i < 4; i++) {
        int g = t + i * 256;
        reinterpret_cast<float4*>(sm + S_WU1)[g] = reinterpret_cast<const float4*>(Wu1)[g];
    }
    #pragma unroll
    for (int i = 0; i < 2; i++) {
        int g = t + i * 256;
        reinterpret_cast<float4*>(sm + S_WU2)[g] = reinterpret_cast<const float4*>(Wu2)[g];
    }
    if (t < 64)        sm[S_B + t] = bm1[t];
    else if (t < 96)   sm[S_B + t] = bm2[t - 64];
    else if (t < 160)  sm[S_B + t] = bu1[t - 96];
    else if (t < 192)  sm[S_B + t] = bu2[t - 160];
    // zero H pad rows 126/127 once (outside G/U overlay extents, never overwritten)
    if (t < 136) sm[S_G + 126 * 68 + t] = 0.f;

    const float rw = *rwp;
    const float cw = 1.f - rw;

    #pragma unroll 1
    for (int it = 0; it < 2; it++) {
        const int b = blockIdx.x * 2 + it;
        if (b >= B) break;

        // ---- load this batch's F (LDG issued before the barrier to overlap) ----
        const float4* Fb4 = reinterpret_cast<const float4*>(Fg + (size_t)b * (NJ * DD));
        float4 pa = Fb4[t];
        float4 pb = Fb4[t + 256];
        __syncthreads();   // prior iter's stage-4 F/U reads complete (and one-time staging on it=0)
        {
            int g = t;
            *reinterpret_cast<float4*>(sm + S_F + (g >> 3) * 36 + (g & 7) * 4) = pa;
            g = t + 256;
            *reinterpret_cast<float4*>(sm + S_F + (g >> 3) * 36 + (g & 7) * 4) = pb;
        }
        __syncthreads();

        // ===== Stage 1: G[64][128] = F @ Wc (+bm1 folded into G1 half) =====
        // Half-warp split: lanes 0-15 and 16-31 cover the SAME 64 cols (weight LDS
        // dedups to 2 wavefronts) but adjacent row-groups (bank-safe: diff 36 floats).
        // side = w>>2 selects col half; q = (w&3)*2 + (lane>>4) is the row-group.
        {
            const int lane   = t & 31;
            const int w      = t >> 5;
            const int side   = w >> 2;
            const int q      = ((w & 3) << 1) + (lane >> 4);
            const int c0     = side * 64 + (lane & 15) * 4;
            uint64_t acc[16];
            uint64_t b0 = 0, b1 = 0;
            if (side == 0) { b0 = ld2s(sm + S_B + c0); b1 = ld2s(sm + S_B + c0 + 2); }
            #pragma unroll
            for (int m = 0; m < 8; m++) { acc[2*m] = b0; acc[2*m + 1] = b1; }

            #pragma unroll
            for (int k4 = 0; k4 < 8; k4++) {
                float fa[8][4];
                #pragma unroll
                for (int m = 0; m < 8; m++) {
                    float4 v = *reinterpret_cast<const float4*>(sm + S_F + (q + 8*m) * 36 + k4 * 4);
                    fa[m][0] = v.x; fa[m][1] = v.y; fa[m][2] = v.z; fa[m][3] = v.w;
                }
                #pragma unroll
                for (int kk = 0; kk < 4; kk++) {
                    ulonglong2 w2 = *reinterpret_cast<const ulonglong2*>(
                        sm + S_WC + (k4 * 4 + kk) * 128 + c0);
                    #pragma unroll
                    for (int m = 0; m < 8; m++) {
                        uint64_t a2 = dup2(fa[m][kk]);
                        fma2(acc[2*m + 0], a2, w2.x);
                        fma2(acc[2*m + 1], a2, w2.y);
                    }
                }
            }
            #pragma unroll
            for (int m = 0; m < 8; m++) {
                ulonglong2 o; o.x = acc[2*m]; o.y = acc[2*m + 1];
                *reinterpret_cast<ulonglong2*>(sm + S_G + (q + 8*m) * 132 + c0) = o;
            }
        }
        __syncthreads();

        // ===== Stage 2a: h1[126][64] = relu(G1[dn] + G2[sn]) (bias already in G1) =====
        {
            float4 h[8];
            const int e  = t >> 1;
            const int d0 = (t & 1) * 32;
            const bool active = (t < 252);
            int dn, sn;
            if (e < 63) { dn = e;      sn = e + 1; }
            else        { dn = e - 62; sn = e - 63; }
            if (active) {
                #pragma unroll
                for (int q = 0; q < 8; q++) {
                    float4 g1 = *reinterpret_cast<const float4*>(sm + S_G + dn * 132 + d0 + q * 4);
                    float4 g2 = *reinterpret_cast<const float4*>(sm + S_G + sn * 132 + 64 + d0 + q * 4);
                    h[q].x = fmaxf(g1.x + g2.x, 0.f);
                    h[q].y = fmaxf(g1.y + g2.y, 0.f);
                    h[q].z = fmaxf(g1.z + g2.z, 0.f);
                    h[q].w = fmaxf(g1.w + g2.w, 0.f);
                }
            }
            __syncthreads();   // all G reads complete before H overlays G
            if (active) {
                #pragma unroll
                for (int q = 0; q < 8; q++)
                    *reinterpret_cast<float4*>(sm + S_G + e * 68 + d0 + q * 4) = h[q];
            }
        }
        __syncthreads();

        // ===== Stage 2b (warps 0-3)  ∥  Stage 3 F-half (warps 4-7) =====
        // Warps 0-3: msg[126][32] = relu(H @ Wm2 + bm2), two-phase scatter to M.
        // Warps 4-7: concurrently accumulate U_F = bu1 + F @ Wu1[0:32] in regs
        //            (depends only on F and Wu1, both stable). After M completes,
        //            warps 4-7 add the M-half, relu, and store U.
        {
            uint64_t acc[16];
            const int c0b = (t & 7) * 4;        // 2b col base (t<128)
            const int pb  = t >> 3;             // 2b row base
            const int ts  = t - 128;
            const int c0s = (ts & 15) * 4;      // stage-3 col base (t>=128)
            const int ps  = ts >> 4;            // stage-3 row base
            if (t < 128) {
                const uint64_t b0 = ld2s(sm + S_B + 64 + c0b);
                const uint64_t b1 = ld2s(sm + S_B + 64 + c0b + 2);
                #pragma unroll
                for (int m = 0; m < 8; m++) { acc[2*m] = b0; acc[2*m + 1] = b1; }
                #pragma unroll
                for (int k4 = 0; k4 < 16; k4++) {
                    float ha[8][4];
                    #pragma unroll
                    for (int m = 0; m < 8; m++) {
                        float4 v = *reinterpret_cast<const float4*>(
                            sm + S_G + (pb + 16*m) * 68 + k4 * 4);
                        ha[m][0] = v.x; ha[m][1] = v.y; ha[m][2] = v.z; ha[m][3] = v.w;
                    }
                    #pragma unroll
                    for (int kk = 0; kk < 4; kk++) {
                        ulonglong2 w2 = *reinterpret_cast<const ulonglong2*>(
                            sm + S_WM2 + (k4 * 4 + kk) * 32 + c0b);
                        #pragma unroll
                        for (int m = 0; m < 8; m++) {
                            uint64_t a2 = dup2(ha[m][kk]);
                            fma2(acc[2*m + 0], a2, w2.x);
                            fma2(acc[2*m + 1], a2, w2.y);
                        }
                    }
                }
                #pragma unroll
                for (int i = 0; i < 16; i++) relu2(acc[i]);
                // phase A: forward edges (row < 63) store M[row]
                #pragma unroll
                for (int m = 0; m < 8; m++) {
                    int r = pb + 16 * m;
                    if (r < 63) {
                        ulonglong2 o; o.x = acc[2*m]; o.y = acc[2*m + 1];
                        *reinterpret_cast<ulonglong2*>(sm + S_M + r * 36 + c0b) = o;
                    }
                }
            } else {
                // stage-3 F-half: acc = bu1 + F @ Wu1[0:32]
                const uint64_t b0 = ld2s(sm + S_B + 96 + c0s);
                const uint64_t b1 = ld2s(sm + S_B + 96 + c0s + 2);
                #pragma unroll
                for (int m = 0; m < 8; m++) { acc[2*m] = b0; acc[2*m + 1] = b1; }
                #pragma unroll
                for (int k4 = 0; k4 < 8; k4++) {
                    float fa[8][4];
                    #pragma unroll
                    for (int m = 0; m < 8; m++) {
                        float4 v = *reinterpret_cast<const float4*>(
                            sm + S_F + (ps + 8*m) * 36 + k4 * 4);
                        fa[m][0] = v.x; fa[m][1] = v.y; fa[m][2] = v.z; fa[m][3] = v.w;
                    }
                    #pragma unroll
                    for (int kk = 0; kk < 4; kk++) {
                        ulonglong2 w2 = *reinterpret_cast<const ulonglong2*>(
                            sm + S_WU1 + (k4 * 4 + kk) * 64 + c0s);
                        #pragma unroll
                        for (int m = 0; m < 8; m++) {
                            uint64_t a2 = dup2(fa[m][kk]);
                            fma2(acc[2*m + 0], a2, w2.x);
                            fma2(acc[2*m + 1], a2, w2.y);
                        }
                    }
                }
            }
            __syncthreads();
            // phase B: backward edges (63 <= r < 126) accumulate into M[r-62];
            // r == 125 is the sole writer of node 63 -> plain store.
            if (t < 128) {
                #pragma unroll
                for (int m = 0; m < 8; m++) {
                    int r = pb + 16 * m;
                    if (r >= 63 && r < 126) {
                        float* mp = sm + S_M + (r - 62) * 36 + c0b;
                        F2 x0; x0.u = acc[2*m];
                        F2 x1; x1.u = acc[2*m + 1];
                        if (r == 125) {
                            mp[0] = x0.f.x; mp[1] = x0.f.y; mp[2] = x1.f.x; mp[3] = x1.f.y;
                        } else {
                            mp[0] += x0.f.x; mp[1] += x0.f.y; mp[2] += x1.f.x; mp[3] += x1.f.y;
                        }
                    }
                }
            }
            __syncthreads();
            // stage-3 M-half (warps 4-7): acc += M @ Wu1[32:64]; relu; store U over H
            if (t >= 128) {
                #pragma unroll
                for (int k4 = 0; k4 < 8; k4++) {
                    float fa[8][4];
                    #pragma unroll
                    for (int m = 0; m < 8; m++) {
                        float4 v = *reinterpret_cast<const float4*>(
                            sm + S_M + (ps + 8*m) * 36 + k4 * 4);
                        fa[m][0] = v.x; fa[m][1] = v.y; fa[m][2] = v.z; fa[m][3] = v.w;
                    }
                    #pragma unroll
                    for (int kk = 0; kk < 4; kk++) {
                        ulonglong2 w2 = *reinterpret_cast<const ulonglong2*>(
                            sm + S_WU1 + (32 + k4 * 4 + kk) * 64 + c0s);
                        #pragma unroll
                        for (int m = 0; m < 8; m++) {
                            uint64_t a2 = dup2(fa[m][kk]);
                            fma2(acc[2*m + 0], a2, w2.x);
                            fma2(acc[2*m + 1], a2, w2.y);
                        }
                    }
                }
                #pragma unroll
                for (int m = 0; m < 8; m++) {
                    relu2(acc[2*m]); relu2(acc[2*m + 1]);
                    ulonglong2 o; o.x = acc[2*m]; o.y = acc[2*m + 1];
                    *reinterpret_cast<ulonglong2*>(sm + S_G + (ps + 8*m) * 68 + c0s) = o;
                }
            }
        }
        __syncthreads();

        // ===== Stage 4: out = rw*(U @ Wu2 + bu2) + (1-rw)*F =====
        if (t < 128) {
            uint64_t acc[8];
            const int c0 = (t & 7) * 4;
            const int p  = t >> 3;
            const uint64_t b0 = ld2s(sm + S_B + 160 + c0);
            const uint64_t b1 = ld2s(sm + S_B + 160 + c0 + 2);
            #pragma unroll
            for (int m = 0; m < 4; m++) { acc[2*m] = b0; acc[2*m + 1] = b1; }

            #pragma unroll
            for (int k4 = 0; k4 < 16; k4++) {
                float ua[4][4];
                #pragma unroll
                for (int m = 0; m < 4; m++) {
                    float4 v = *reinterpret_cast<const float4*>(
                        sm + S_G + (p + 16*m) * 68 + k4 * 4);
                    ua[m][0] = v.x; ua[m][1] = v.y; ua[m][2] = v.z; ua[m][3] = v.w;
                }
                #pragma unroll
                for (int kk = 0; kk < 4; kk++) {
                    ulonglong2 w2 = *reinterpret_cast<const ulonglong2*>(
                        sm + S_WU2 + (k4 * 4 + kk) * 32 + c0);
                    #pragma unroll
                    for (int m = 0; m < 4; m++) {
                        uint64_t a2 = dup2(ua[m][kk]);
                        fma2(acc[2*m + 0], a2, w2.x);
                        fma2(acc[2*m + 1], a2, w2.y);
                    }
                }
            }
            #pragma unroll
            for (int m = 0; m < 4; m++) {
                const int r = p + 16 * m;
                float4 fv = *reinterpret_cast<const float4*>(sm + S_F + r * 36 + c0);
                F2 x0; x0.u = acc[2*m];
                F2 x1; x1.u = acc[2*m + 1];
                float4 o;
                o.x = rw * x0.f.x + cw * fv.x;
                o.y = rw * x0.f.y + cw * fv.y;
                o.z = rw * x1.f.x + cw * fv.z;
                o.w = rw * x1.f.y + cw * fv.w;
                *reinterpret_cast<float4*>(Og + (size_t)b * 2048 + r * 32 + c0) = o;
            }
        }
    }
}

extern "C" void kernel_launch(void* const* d_in, const int* in_sizes, int n_in,
                              void* d_out, int out_size) {
    const float* Fg  = (const float*)d_in[0];
    const float* Wm1 = (const float*)d_in[1];
    const float* bm1 = (const float*)d_in[2];
    const float* Wm2 = (const float*)d_in[3];
    const float* bm2 = (const float*)d_in[4];
    const float* Wu1 = (const float*)d_in[5];
    const float* bu1 = (const float*)d_in[6];
    const float* Wu2 = (const float*)d_in[7];
    const float* bu2 = (const float*)d_in[8];
    const float* rwp = (const float*)d_in[9];
    float* Og = (float*)d_out;

    const int B = in_sizes[0] / (NJ * DD);
    const int smem_bytes = S_TOTAL * sizeof(float);   // 103168

    static bool attr_set = false;
    if (!attr_set) {
        cudaFuncSetAttribute(agn_kernel,
                             cudaFuncAttributeMaxDynamicSharedMemorySize, smem_bytes);
        attr_set = true;
    }

    const int grid = (B + 1) / 2;   // 2 batches per CTA
    agn_kernel<<<grid, 256, smem_bytes>>>(Fg, Wm1, bm1, Wm2, bm2,
                                          Wu1, bu1, Wu2, bu2, rwp, Og, B);
}

// round 17
// speedup vs baseline: 1.0017x; 1.0017x over previous
#include <cuda_runtime.h>
#include <cstdint>

#define NJ 64
#define DD 32
#define HH 64

// Shared memory layout (float offsets)
#define S_WC   0                    // Wm1 rearranged [32][128] = 4096
#define S_WM2  (S_WC + 4096)        // [64][32] = 2048
#define S_WU1  (S_WM2 + 2048)       // [64][64] = 4096
#define S_WU2  (S_WU1 + 4096)       // [64][32] = 2048
#define S_B    (S_WU2 + 2048)       // bm1[0:64) bm2[64:96) bu1[96:160) bu2[160:192)
#define S_F    (S_B + 192)          // [64][36] = 2304
#define S_M    (S_F + 2304)         // [64][36] = 2304
#define S_G    (S_M + 2304)         // G[64][132]=8448 ; overlays: H[128][68]=8704 ; U[64][68]
#define S_TOTAL (S_G + 8704)        // 25792 floats = 103168 bytes

union F2 { uint64_t u; float2 f; };

__device__ __forceinline__ uint64_t ld2s(const float* p) {
    return *reinterpret_cast<const uint64_t*>(p);
}
__device__ __forceinline__ void fma2(uint64_t& d, uint64_t a, uint64_t b) {
    asm("fma.rn.f32x2 %0, %1, %2, %0;" : "+l"(d) : "l"(a), "l"(b));
}
__device__ __forceinline__ uint64_t dup2(float a) {
    uint64_t r; asm("mov.b64 %0, {%1, %1};" : "=l"(r) : "f"(a)); return r;
}
__device__ __forceinline__ void relu2(uint64_t& v) {
    F2 x; x.u = v;
    x.f.x = fmaxf(x.f.x, 0.f);
    x.f.y = fmaxf(x.f.y, 0.f);
    v = x.u;
}

extern __shared__ float sm[];

__global__ void __launch_bounds__(256, 2)
agn_kernel(const float* __restrict__ Fg,
           const float* __restrict__ Wm1, const float* __restrict__ bm1,
           const float* __restrict__ Wm2, const float* __restrict__ bm2,
           const float* __restrict__ Wu1, const float* __restrict__ bu1,
           const float* __restrict__ Wu2, const float* __restrict__ bu2,
           const float* __restrict__ rwp,
           float* __restrict__ Og, int B)
{
    const int t = threadIdx.x;

    // ================= one-time: stage weights / biases, zero H pad rows ==========
    // Wc[32][128]: Wc[k][c] = Wm1[k][c] for c<64 ; Wm1[k+32][c-64] for c>=64
    #pragma unroll
    for (int i = 0; i < 16; i++) {
        int gi = t + i * 256;
        int kg = gi >> 6, h = gi & 63;
        sm[S_WC + (kg & 31) * 128 + (kg >> 5) * 64 + h] = Wm1[gi];
    }
    #pragma unroll
    for (int i = 0; i < 2; i++) {
        int g = t + i * 256;
        reinterpret_cast<float4*>(sm + S_WM2)[g] = reinterpret_cast<const float4*>(Wm2)[g];
    }
    #pragma unroll
    for (int i = 0; i < 4; i++) {
        int g = t + i * 256;
        reinterpret_cast<float4*>(sm + S_WU1)[g] = reinterpret_cast<const float4*>(Wu1)[g];
    }
    #pragma unroll
    for (int i = 0; i < 2; i++) {
        int g = t + i * 256;
        reinterpret_cast<float4*>(sm + S_WU2)[g] = reinterpret_cast<const float4*>(Wu2)[g];
    }
    if (t < 64)        sm[S_B + t] = bm1[t];
    else if (t < 96)   sm[S_B + t] = bm2[t - 64];
    else if (t < 160)  sm[S_B + t] = bu1[t - 96];
    else if (t < 192)  sm[S_B + t] = bu2[t - 160];
    // zero H pad rows 126/127 once (outside G/U overlay extents, never overwritten)
    if (t < 136) sm[S_G + 126 * 68 + t] = 0.f;

    const float rw = *rwp;
    const float cw = 1.f - rw;

    #pragma unroll 1
    for (int it = 0; it < 2; it++) {
        const int b = blockIdx.x * 2 + it;
        if (b >= B) break;

        // ---- load this batch's F (LDG issued before the barrier to overlap) ----
        const float4* Fb4 = reinterpret_cast<const float4*>(Fg + (size_t)b * (NJ * DD));
        float4 pa = Fb4[t];
        float4 pb = Fb4[t + 256];
        __syncthreads();   // prior iter's stage-4 F/U reads complete (and one-time staging on it=0)
        {
            int g = t;
            *reinterpret_cast<float4*>(sm + S_F + (g >> 3) * 36 + (g & 7) * 4) = pa;
            g = t + 256;
            *reinterpret_cast<float4*>(sm + S_F + (g >> 3) * 36 + (g & 7) * 4) = pb;
        }
        __syncthreads();

        // ===== Stage 1: G[64][128] = F @ Wc (+bm1 folded into G1 half) =====
        // Half-warp split: lanes 0-15 and 16-31 cover the SAME 64 cols (weight LDS
        // dedups to 2 wavefronts) but adjacent row-groups (bank-safe: diff 36 floats).
        // side = w>>2 selects col half; q = (w&3)*2 + (lane>>4) is the row-group.
        {
            const int lane   = t & 31;
            const int w      = t >> 5;
            const int side   = w >> 2;
            const int q      = ((w & 3) << 1) + (lane >> 4);
            const int c0     = side * 64 + (lane & 15) * 4;
            uint64_t acc[16];
            uint64_t b0 = 0, b1 = 0;
            if (side == 0) { b0 = ld2s(sm + S_B + c0); b1 = ld2s(sm + S_B + c0 + 2); }
            #pragma unroll
            for (int m = 0; m < 8; m++) { acc[2*m] = b0; acc[2*m + 1] = b1; }

            #pragma unroll
            for (int k4 = 0; k4 < 8; k4++) {
                float fa[8][4];
                #pragma unroll
                for (int m = 0; m < 8; m++) {
                    float4 v = *reinterpret_cast<const float4*>(sm + S_F + (q + 8*m) * 36 + k4 * 4);
                    fa[m][0] = v.x; fa[m][1] = v.y; fa[m][2] = v.z; fa[m][3] = v.w;
                }
                #pragma unroll
                for (int kk = 0; kk < 4; kk++) {
                    ulonglong2 w2 = *reinterpret_cast<const ulonglong2*>(
                        sm + S_WC + (k4 * 4 + kk) * 128 + c0);
                    #pragma unroll
                    for (int m = 0; m < 8; m++) {
                        uint64_t a2 = dup2(fa[m][kk]);
                        fma2(acc[2*m + 0], a2, w2.x);
                        fma2(acc[2*m + 1], a2, w2.y);
                    }
                }
            }
            #pragma unroll
            for (int m = 0; m < 8; m++) {
                ulonglong2 o; o.x = acc[2*m]; o.y = acc[2*m + 1];
                *reinterpret_cast<ulonglong2*>(sm + S_G + (q + 8*m) * 132 + c0) = o;
            }
        }
        __syncthreads();

        // ===== Stage 2a: h1[126][64] = relu(G1[dn] + G2[sn]) (bias already in G1) =====
        {
            float4 h[8];
            const int e  = t >> 1;
            const int d0 = (t & 1) * 32;
            const bool active = (t < 252);
            int dn, sn;
            if (e < 63) { dn = e;      sn = e + 1; }
            else        { dn = e - 62; sn = e - 63; }
            if (active) {
                #pragma unroll
                for (int q = 0; q < 8; q++) {
                    float4 g1 = *reinterpret_cast<const float4*>(sm + S_G + dn * 132 + d0 + q * 4);
                    float4 g2 = *reinterpret_cast<const float4*>(sm + S_G + sn * 132 + 64 + d0 + q * 4);
                    h[q].x = fmaxf(g1.x + g2.x, 0.f);
                    h[q].y = fmaxf(g1.y + g2.y, 0.f);
                    h[q].z = fmaxf(g1.z + g2.z, 0.f);
                    h[q].w = fmaxf(g1.w + g2.w, 0.f);
                }
            }
            __syncthreads();   // all G reads complete before H overlays G
            if (active) {
                #pragma unroll
                for (int q = 0; q < 8; q++)
                    *reinterpret_cast<float4*>(sm + S_G + e * 68 + d0 + q * 4) = h[q];
            }
        }
        __syncthreads();

        // ===== Stage 2b (warps 0-3)  ∥  Stage 3 F-half (warps 4-7) =====
        // Warps 0-3: msg[126][32] = relu(H @ Wm2 + bm2), two-phase scatter to M.
        // Warps 4-7: concurrently accumulate U_F = bu1 + F @ Wu1[0:32] in regs
        //            (depends only on F and Wu1, both stable). After M completes,
        //            warps 4-7 add the M-half, relu, and store U.
        {
            uint64_t acc[16];
            const int c0b = (t & 7) * 4;        // 2b col base (t<128)
            const int pb  = t >> 3;             // 2b row base
            const int ts  = t - 128;
            const int c0s = (ts & 15) * 4;      // stage-3 col base (t>=128)
            const int ps  = ts >> 4;            // stage-3 row base
            if (t < 128) {
                const uint64_t b0 = ld2s(sm + S_B + 64 + c0b);
                const uint64_t b1 = ld2s(sm + S_B + 64 + c0b + 2);
                #pragma unroll
                for (int m = 0; m < 8; m++) { acc[2*m] = b0; acc[2*m + 1] = b1; }
                #pragma unroll
                for (int k4 = 0; k4 < 16; k4++) {
                    float ha[8][4];
                    #pragma unroll
                    for (int m = 0; m < 8; m++) {
                        float4 v = *reinterpret_cast<const float4*>(
                            sm + S_G + (pb + 16*m) * 68 + k4 * 4);
                        ha[m][0] = v.x; ha[m][1] = v.y; ha[m][2] = v.z; ha[m][3] = v.w;
                    }
                    #pragma unroll
                    for (int kk = 0; kk < 4; kk++) {
                        ulonglong2 w2 = *reinterpret_cast<const ulonglong2*>(
                            sm + S_WM2 + (k4 * 4 + kk) * 32 + c0b);
                        #pragma unroll
                        for (int m = 0; m < 8; m++) {
                            uint64_t a2 = dup2(ha[m][kk]);
                            fma2(acc[2*m + 0], a2, w2.x);
                            fma2(acc[2*m + 1], a2, w2.y);
                        }
                    }
                }
                #pragma unroll
                for (int i = 0; i < 16; i++) relu2(acc[i]);
                // phase A: forward edges (row < 63) store M[row]
                #pragma unroll
                for (int m = 0; m < 8; m++) {
                    int r = pb + 16 * m;
                    if (r < 63) {
                        ulonglong2 o; o.x = acc[2*m]; o.y = acc[2*m + 1];
                        *reinterpret_cast<ulonglong2*>(sm + S_M + r * 36 + c0b) = o;
                    }
                }
            } else {
                // stage-3 F-half: acc = bu1 + F @ Wu1[0:32]
                const uint64_t b0 = ld2s(sm + S_B + 96 + c0s);
                const uint64_t b1 = ld2s(sm + S_B + 96 + c0s + 2);
                #pragma unroll
                for (int m = 0; m < 8; m++) { acc[2*m] = b0; acc[2*m + 1] = b1; }
                #pragma unroll
                for (int k4 = 0; k4 < 8; k4++) {
                    float fa[8][4];
                    #pragma unroll
                    for (int m = 0; m < 8; m++) {
                        float4 v = *reinterpret_cast<const float4*>(
                            sm + S_F + (ps + 8*m) * 36 + k4 * 4);
                        fa[m][0] = v.x; fa[m][1] = v.y; fa[m][2] = v.z; fa[m][3] = v.w;
                    }
                    #pragma unroll
                    for (int kk = 0; kk < 4; kk++) {
                        ulonglong2 w2 = *reinterpret_cast<const ulonglong2*>(
                            sm + S_WU1 + (k4 * 4 + kk) * 64 + c0s);
                        #pragma unroll
                        for (int m = 0; m < 8; m++) {
                            uint64_t a2 = dup2(fa[m][kk]);
                            fma2(acc[2*m + 0], a2, w2.x);
                            fma2(acc[2*m + 1], a2, w2.y);
                        }
                    }
                }
            }
            __syncthreads();
            // phase B: backward edges (63 <= r < 126) accumulate into M[r-62];
            // r == 125 is the sole writer of node 63 -> plain store.
            if (t < 128) {
                #pragma unroll
                for (int m = 0; m < 8; m++) {
                    int r = pb + 16 * m;
                    if (r >= 63 && r < 126) {
                        float* mp = sm + S_M + (r - 62) * 36 + c0b;
                        F2 x0; x0.u = acc[2*m];
                        F2 x1; x1.u = acc[2*m + 1];
                        if (r == 125) {
                            mp[0] = x0.f.x; mp[1] = x0.f.y; mp[2] = x1.f.x; mp[3] = x1.f.y;
                        } else {
                            mp[0] += x0.f.x; mp[1] += x0.f.y; mp[2] += x1.f.x; mp[3] += x1.f.y;
                        }
                    }
                }
            }
            __syncthreads();
            // stage-3 M-half (warps 4-7): acc += M @ Wu1[32:64]; relu; store U over H
            if (t >= 128) {
                #pragma unroll
                for (int k4 = 0; k4 < 8; k4++) {
                    float fa[8][4];
                    #pragma unroll
                    for (int m = 0; m < 8; m++) {
                        float4 v = *reinterpret_cast<const float4*>(
                            sm + S_M + (ps + 8*m) * 36 + k4 * 4);
                        fa[m][0] = v.x; fa[m][1] = v.y; fa[m][2] = v.z; fa[m][3] = v.w;
                    }
                    #pragma unroll
                    for (int kk = 0; kk < 4; kk++) {
                        ulonglong2 w2 = *reinterpret_cast<const ulonglong2*>(
                            sm + S_WU1 + (32 + k4 * 4 + kk) * 64 + c0s);
                        #pragma unroll
                        for (int m = 0; m < 8; m++) {
                            uint64_t a2 = dup2(fa[m][kk]);
                            fma2(acc[2*m + 0], a2, w2.x);
                            fma2(acc[2*m + 1], a2, w2.y);
                        }
                    }
                }
                #pragma unroll
                for (int m = 0; m < 8; m++) {
                    relu2(acc[2*m]); relu2(acc[2*m + 1]);
                    ulonglong2 o; o.x = acc[2*m]; o.y = acc[2*m + 1];
                    *reinterpret_cast<ulonglong2*>(sm + S_G + (ps + 8*m) * 68 + c0s) = o;
                }
            }
        }
        __syncthreads();

        // ===== Stage 4: out = rw*(U @ Wu2 + bu2) + (1-rw)*F =====
        if (t < 128) {
            uint64_t acc[8];
            const int c0 = (t & 7) * 4;
            const int p  = t >> 3;
            const uint64_t b0 = ld2s(sm + S_B + 160 + c0);
            const uint64_t b1 = ld2s(sm + S_B + 160 + c0 + 2);
            #pragma unroll
            for (int m = 0; m < 4; m++) { acc[2*m] = b0; acc[2*m + 1] = b1; }

            #pragma unroll
            for (int k4 = 0; k4 < 16; k4++) {
                float ua[4][4];
                #pragma unroll
                for (int m = 0; m < 4; m++) {
                    float4 v = *reinterpret_cast<const float4*>(
                        sm + S_G + (p + 16*m) * 68 + k4 * 4);
                    ua[m][0] = v.x; ua[m][1] = v.y; ua[m][2] = v.z; ua[m][3] = v.w;
                }
                #pragma unroll
                for (int kk = 0; kk < 4; kk++) {
                    ulonglong2 w2 = *reinterpret_cast<const ulonglong2*>(
                        sm + S_WU2 + (k4 * 4 + kk) * 32 + c0);
                    #pragma unroll
                    for (int m = 0; m < 4; m++) {
                        uint64_t a2 = dup2(ua[m][kk]);
                        fma2(acc[2*m + 0], a2, w2.x);
                        fma2(acc[2*m + 1], a2, w2.y);
                    }
                }
            }
            #pragma unroll
            for (int m = 0; m < 4; m++) {
                const int r = p + 16 * m;
                float4 fv = *reinterpret_cast<const float4*>(sm + S_F + r * 36 + c0);
                F2 x0; x0.u = acc[2*m];
                F2 x1; x1.u = acc[2*m + 1];
                float4 o;
                o.x = rw * x0.f.x + cw * fv.x;
                o.y = rw * x0.f.y + cw * fv.y;
                o.z = rw * x1.f.x + cw * fv.z;
                o.w = rw * x1.f.y + cw * fv.w;
                *reinterpret_cast<float4*>(Og + (size_t)b * 2048 + r * 32 + c0) = o;
            }
        }
    }
}

extern "C" void kernel_launch(void* const* d_in, const int* in_sizes, int n_in,
                              void* d_out, int out_size) {
    const float* Fg  = (const float*)d_in[0];
    const float* Wm1 = (const float*)d_in[1];
    const float* bm1 = (const float*)d_in[2];
    const float* Wm2 = (const float*)d_in[3];
    const float* bm2 = (const float*)d_in[4];
    const float* Wu1 = (const float*)d_in[5];
    const float* bu1 = (const float*)d_in[6];
    const float* Wu2 = (const float*)d_in[7];
    const float* bu2 = (const float*)d_in[8];
    const float* rwp = (const float*)d_in[9];
    float* Og = (float*)d_out;

    const int B = in_sizes[0] / (NJ * DD);
    const int smem_bytes = S_TOTAL * sizeof(float);   // 103168

    static bool attr_set = false;
    if (!attr_set) {
        cudaFuncSetAttribute(agn_kernel,
                             cudaFuncAttributeMaxDynamicSharedMemorySize, smem_bytes);
        attr_set = true;
    }

    const int grid = (B + 1) / 2;   // 2 batches per CTA
    agn_kernel<<<grid, 256, smem_bytes>>>(Fg, Wm1, bm1, Wm2, bm2,
                                          Wu1, bu1, Wu2, bu2, rwp, Og, B);
}